// round 14
// baseline (speedup 1.0000x reference)
#include <cuda_runtime.h>
#include <math.h>
#include <stdint.h>

// Problem dims
#define B_  16
#define C_  256
#define H_  128
#define W_  128
#define HW  (H_ * W_)         // 16384
#define HW4 (HW / 4)          // 4096 float4 per plane
#define PH  (B_ * HW)         // phase stride in g_mp (262144 floats)

// Device scratch (no allocation allowed)
__device__ float g_mp[4 * PH];        // partial channel sums [phase][b][h][w]
__device__ float g_cf[B_ * C_];       // sigmoid gate [b][c]
__device__ float g_Pt[B_ * HW];       // (C*m) transposed: [b][w][u]
__device__ float g_Qt[B_ * HW];       // (S*m) transposed: [b][w][u]
__device__ float g_sf[B_ * HW];       // sf [b][h][w]

// ---- PDL controls -----------------------------------------------------------
__device__ __forceinline__ void grid_wait() {
    asm volatile("griddepcontrol.wait;" ::: "memory");
}
__device__ __forceinline__ void grid_launch_dependents() {
    asm volatile("griddepcontrol.launch_dependents;" ::: "memory");
}

// ---- packed f32x2 helpers (Blackwell) --------------------------------------
__device__ __forceinline__ uint64_t pk2(float lo, float hi) {
    uint64_t r;
    asm("mov.b64 %0, {%1, %2};" : "=l"(r) : "f"(lo), "f"(hi));
    return r;
}
__device__ __forceinline__ void upk2(uint64_t v, float& lo, float& hi) {
    asm("mov.b64 {%0, %1}, %2;" : "=f"(lo), "=f"(hi) : "l"(v));
}
__device__ __forceinline__ uint64_t fma2(uint64_t a, uint64_t b, uint64_t c) {
    uint64_t r;
    asm("fma.rn.f32x2 %0, %1, %2, %3;" : "=l"(r) : "l"(a), "l"(b), "l"(c));
    return r;
}
__device__ __forceinline__ void lds_v2u64(unsigned addr, uint64_t& a, uint64_t& b) {
    asm("ld.shared.v2.u64 {%0, %1}, [%2];" : "=l"(a), "=l"(b) : "r"(addr));
}

// ---------------------------------------------------------------------------
// Kernel 1 (merged): blocks 0..4095  -> partial channel sums (64 ch each)
//                    blocks 4096..4159 -> cf gate
// 8 accumulator streams -> ~48 independent loads in flight per thread
// (per-warp outstanding-LDG cap is ~55 on B300; 32 was measurably short).
// ---------------------------------------------------------------------------
__global__ void __launch_bounds__(64) mean_cf_kernel(
        const float4* __restrict__ x,
        const float* __restrict__ Wm,
        const float* __restrict__ bias) {
    if (blockIdx.x < 4096) {
        int phase = blockIdx.x >> 10;                      // 0..3
        int t = (blockIdx.x & 1023) * 64 + threadIdx.x;    // 0 .. 65535
        int b = t >> 12;
        int pos = t & 4095;
        int c0 = phase * 64;
        const float4* p = x + (size_t)b * C_ * HW4 + (size_t)c0 * HW4 + pos;
        float4 a0 = make_float4(0.f, 0.f, 0.f, 0.f);
        float4 a1 = make_float4(0.f, 0.f, 0.f, 0.f);
        float4 a2 = make_float4(0.f, 0.f, 0.f, 0.f);
        float4 a3 = make_float4(0.f, 0.f, 0.f, 0.f);
        float4 a4 = make_float4(0.f, 0.f, 0.f, 0.f);
        float4 a5 = make_float4(0.f, 0.f, 0.f, 0.f);
        float4 a6 = make_float4(0.f, 0.f, 0.f, 0.f);
        float4 a7 = make_float4(0.f, 0.f, 0.f, 0.f);
#pragma unroll 8
        for (int c = 0; c < 64; c += 8) {
            float4 v0 = p[(size_t)(c + 0) * HW4];
            float4 v1 = p[(size_t)(c + 1) * HW4];
            float4 v2 = p[(size_t)(c + 2) * HW4];
            float4 v3 = p[(size_t)(c + 3) * HW4];
            float4 v4 = p[(size_t)(c + 4) * HW4];
            float4 v5 = p[(size_t)(c + 5) * HW4];
            float4 v6 = p[(size_t)(c + 6) * HW4];
            float4 v7 = p[(size_t)(c + 7) * HW4];
            a0.x += v0.x; a0.y += v0.y; a0.z += v0.z; a0.w += v0.w;
            a1.x += v1.x; a1.y += v1.y; a1.z += v1.z; a1.w += v1.w;
            a2.x += v2.x; a2.y += v2.y; a2.z += v2.z; a2.w += v2.w;
            a3.x += v3.x; a3.y += v3.y; a3.z += v3.z; a3.w += v3.w;
            a4.x += v4.x; a4.y += v4.y; a4.z += v4.z; a4.w += v4.w;
            a5.x += v5.x; a5.y += v5.y; a5.z += v5.z; a5.w += v5.w;
            a6.x += v6.x; a6.y += v6.y; a6.z += v6.z; a6.w += v6.w;
            a7.x += v7.x; a7.y += v7.y; a7.z += v7.z; a7.w += v7.w;
        }
        float4 acc;
        acc.x = ((a0.x + a1.x) + (a2.x + a3.x)) + ((a4.x + a5.x) + (a6.x + a7.x));
        acc.y = ((a0.y + a1.y) + (a2.y + a3.y)) + ((a4.y + a5.y) + (a6.y + a7.y));
        acc.z = ((a0.z + a1.z) + (a2.z + a3.z)) + ((a4.z + a5.z) + (a6.z + a7.z));
        acc.w = ((a0.w + a1.w) + (a2.w + a3.w)) + ((a4.w + a5.w) + (a6.w + a7.w));
        ((float4*)g_mp)[phase * (PH / 4) + t] = acc;
        grid_launch_dependents();
    } else {
        __shared__ __align__(16) float xs[C_];
        int cb = blockIdx.x - 4096;
        int b  = cb >> 2;
        int c0 = (cb & 3) * 64;
        const float* xf = (const float*)x;
#pragma unroll
        for (int k = 0; k < 4; ++k) {
            int ch = threadIdx.x * 4 + k;
            xs[ch] = xf[((size_t)(b * C_ + ch)) * HW];     // x[b,ch,0,0]
        }
        __syncthreads();
        int c = c0 + threadIdx.x;
        float acc = bias[c];
        const float4* wr = (const float4*)(Wm + (size_t)c * C_);
        const float4* xv = (const float4*)xs;
#pragma unroll 8
        for (int k = 0; k < C_ / 4; ++k) {
            float4 w4 = wr[k];
            float4 x4 = xv[k];
            acc += w4.x * x4.x + w4.y * x4.y + w4.z * x4.z + w4.w * x4.w;
        }
        g_cf[b * C_ + c] = 1.0f / (1.0f + expf(-acc));
        grid_launch_dependents();
    }
}

// ---------------------------------------------------------------------------
// DFT stage 1: twiddle preamble runs BEFORE the PDL wait (overlaps mean tail).
// ---------------------------------------------------------------------------
__global__ void dft_stage1(void) {
    __shared__ float twc[128], tws[128];
    __shared__ __align__(16) float mr[128][4];
    __shared__ __align__(16) float me[64][4];   // h = 1..63 used
    __shared__ __align__(16) float mo[64][4];

    int b  = blockIdx.y;
    int wt = blockIdx.x;           // w-tile (4 wide)
    int tid = threadIdx.x;         // 0..127
    int u = tid;

    // --- preamble (no dependency on mean) ---
    {
        float s, c;
        sincospif((float)tid * (1.0f / 64.0f), &s, &c);   // e^{i*2pi*tid/128}
        twc[tid] = c; tws[tid] = s;
    }
    grid_wait();
    // --- dependent loads ---
    {
        const float* mb = g_mp + (size_t)b * HW + wt * 4 + tid * W_;
        float4 p0 = *(const float4*)(mb);
        float4 p1 = *(const float4*)(mb + PH);
        float4 p2 = *(const float4*)(mb + 2 * PH);
        float4 p3 = *(const float4*)(mb + 3 * PH);
        const float sc = 1.0f / 256.0f;
        mr[tid][0] = ((p0.x + p1.x) + (p2.x + p3.x)) * sc;
        mr[tid][1] = ((p0.y + p1.y) + (p2.y + p3.y)) * sc;
        mr[tid][2] = ((p0.z + p1.z) + (p2.z + p3.z)) * sc;
        mr[tid][3] = ((p0.w + p1.w) + (p2.w + p3.w)) * sc;
    }
    __syncthreads();
    if (tid < 63) {
        int h = tid + 1;
#pragma unroll
        for (int c = 0; c < 4; ++c) {
            float a = mr[h][c], d = mr[128 - h][c];
            me[h][c] = a + d;
            mo[h][c] = a - d;
        }
    }
    __syncthreads();

    float cj[8], sj[8], cg[8], sg[8];
    cj[0] = 1.0f; sj[0] = 0.0f;
    cg[0] = 1.0f; sg[0] = 0.0f;
#pragma unroll
    for (int j = 1; j < 8; ++j) {
        int idx = (u * j) & 127;
        cj[j] = twc[idx]; sj[j] = tws[idx];
    }
#pragma unroll
    for (int g = 1; g < 8; ++g) {
        int idx = (u * g * 8) & 127;
        cg[g] = twc[idx]; sg[g] = tws[idx];
    }

    float sgn = (u & 1) ? -1.0f : 1.0f;
    uint64_t aP0 = pk2(mr[0][0] + sgn * mr[64][0], mr[0][1] + sgn * mr[64][1]);
    uint64_t aP1 = pk2(mr[0][2] + sgn * mr[64][2], mr[0][3] + sgn * mr[64][3]);
    uint64_t aQ0 = pk2(0.f, 0.f);
    uint64_t aQ1 = aQ0;

    unsigned sme = (unsigned)__cvta_generic_to_shared(&me[0][0]);
    unsigned smo = (unsigned)__cvta_generic_to_shared(&mo[0][0]);

#pragma unroll
    for (int h = 1; h < 64; ++h) {
        int g = h >> 3, j = h & 7;
        float cw = cg[g] * cj[j] - sg[g] * sj[j];
        float sw = sg[g] * cj[j] + cg[g] * sj[j];
        uint64_t cwp = pk2(cw, cw);
        uint64_t swp = pk2(sw, sw);
        uint64_t e0, e1, o0, o1;
        lds_v2u64(sme + h * 16, e0, e1);
        lds_v2u64(smo + h * 16, o0, o1);
        aP0 = fma2(cwp, e0, aP0);
        aP1 = fma2(cwp, e1, aP1);
        aQ0 = fma2(swp, o0, aQ0);
        aQ1 = fma2(swp, o1, aQ1);
    }

    float p0, p1, p2, p3, q0, q1, q2, q3;
    upk2(aP0, p0, p1); upk2(aP1, p2, p3);
    upk2(aQ0, q0, q1); upk2(aQ1, q2, q3);

    size_t base = (size_t)b * HW;
    int w0 = wt * 4;
    g_Pt[base + (w0 + 0) * 128 + u] = p0;
    g_Pt[base + (w0 + 1) * 128 + u] = p1;
    g_Pt[base + (w0 + 2) * 128 + u] = p2;
    g_Pt[base + (w0 + 3) * 128 + u] = p3;
    g_Qt[base + (w0 + 0) * 128 + u] = q0;
    g_Qt[base + (w0 + 1) * 128 + u] = q1;
    g_Qt[base + (w0 + 2) * 128 + u] = q2;
    g_Qt[base + (w0 + 3) * 128 + u] = q3;
    grid_launch_dependents();
}

// ---------------------------------------------------------------------------
// DFT stage 2: twiddle preamble before PDL wait (overlaps dft_stage1).
// ---------------------------------------------------------------------------
__global__ void dft_stage2(void) {
    __shared__ float twc[128], tws[128];
    __shared__ __align__(16) float pr[128][4];
    __shared__ __align__(16) float qr[128][4];
    __shared__ __align__(16) float pe[64][4];
    __shared__ __align__(16) float qo[64][4];

    int b  = blockIdx.y;
    int ut = blockIdx.x;            // u-tile (4 wide)
    int tid = threadIdx.x;          // 0..127
    int v = tid;

    {
        float s, c;
        sincospif((float)tid * (1.0f / 64.0f), &s, &c);
        twc[tid] = c; tws[tid] = s;
    }
    grid_wait();
    {
        const float* pb = g_Pt + (size_t)b * HW + ut * 4;
        const float* qb = g_Qt + (size_t)b * HW + ut * 4;
        float4 pv = *(const float4*)(pb + tid * 128);
        float4 qv = *(const float4*)(qb + tid * 128);
        pr[tid][0] = pv.x; pr[tid][1] = pv.y; pr[tid][2] = pv.z; pr[tid][3] = pv.w;
        qr[tid][0] = qv.x; qr[tid][1] = qv.y; qr[tid][2] = qv.z; qr[tid][3] = qv.w;
    }
    __syncthreads();
    if (tid < 63) {
        int w = tid + 1;
#pragma unroll
        for (int c = 0; c < 4; ++c) {
            pe[w][c] = pr[w][c] + pr[128 - w][c];
            qo[w][c] = qr[w][c] - qr[128 - w][c];
        }
    }
    __syncthreads();

    float cj[8], sj[8], cg[8], sg[8];
    cj[0] = 1.0f; sj[0] = 0.0f;
    cg[0] = 1.0f; sg[0] = 0.0f;
#pragma unroll
    for (int j = 1; j < 8; ++j) {
        int idx = (v * j) & 127;
        cj[j] = twc[idx]; sj[j] = tws[idx];
    }
#pragma unroll
    for (int g = 1; g < 8; ++g) {
        int idx = (v * g * 8) & 127;
        cg[g] = twc[idx]; sg[g] = tws[idx];
    }

    float sgn = (v & 1) ? -1.0f : 1.0f;
    uint64_t a0 = pk2(pr[0][0] + sgn * pr[64][0], pr[0][1] + sgn * pr[64][1]);
    uint64_t a1 = pk2(pr[0][2] + sgn * pr[64][2], pr[0][3] + sgn * pr[64][3]);

    unsigned spe = (unsigned)__cvta_generic_to_shared(&pe[0][0]);
    unsigned sqo = (unsigned)__cvta_generic_to_shared(&qo[0][0]);

#pragma unroll
    for (int w = 1; w < 64; ++w) {
        int g = w >> 3, j = w & 7;
        float cw = cg[g] * cj[j] - sg[g] * sj[j];
        float sw = sg[g] * cj[j] + cg[g] * sj[j];
        uint64_t cwp = pk2(cw, cw);
        uint64_t nswp = pk2(-sw, -sw);
        uint64_t e0, e1, o0, o1;
        lds_v2u64(spe + w * 16, e0, e1);
        lds_v2u64(sqo + w * 16, o0, o1);
        a0 = fma2(cwp, e0, a0);
        a1 = fma2(cwp, e1, a1);
        a0 = fma2(nswp, o0, a0);
        a1 = fma2(nswp, o1, a1);
    }

    float r0, r1, r2, r3;
    upk2(a0, r0, r1); upk2(a1, r2, r3);

    size_t base = (size_t)b * HW;
    int u0 = ut * 4;
    g_sf[base + (u0 + 0) * 128 + v] = r0;   // coalesced in v
    g_sf[base + (u0 + 1) * 128 + v] = r1;
    g_sf[base + (u0 + 2) * 128 + v] = r2;
    g_sf[base + (u0 + 3) * 128 + v] = r3;
    grid_launch_dependents();
}

// ---------------------------------------------------------------------------
// Kernel 4: out = x * (cf + sf). x loads issued BEFORE the PDL wait.
// ---------------------------------------------------------------------------
__global__ void out_kernel(const float4* __restrict__ x, float4* __restrict__ out) {
    int chunk = gridDim.x - 1 - blockIdx.x;
    int base = chunk * 1024;                    // chunk start (plane-aligned /4)
    int plane = base >> 12;                     // (b*256 + c), constant per block
    int b = plane >> 8;
    int t = threadIdx.x;

    float4 v0 = __ldcs(x + base + t);
    float4 v1 = __ldcs(x + base + 256 + t);
    float4 v2 = __ldcs(x + base + 512 + t);
    float4 v3 = __ldcs(x + base + 768 + t);

    grid_wait();

    float cf = g_cf[plane];
    const float4* sf4 = (const float4*)g_sf + b * HW4 + (base & 4095);
    float4 f0 = sf4[t];
    float4 f1 = sf4[256 + t];
    float4 f2 = sf4[512 + t];
    float4 f3 = sf4[768 + t];

    float4 o0, o1, o2, o3;
    o0.x = v0.x * (cf + f0.x); o0.y = v0.y * (cf + f0.y);
    o0.z = v0.z * (cf + f0.z); o0.w = v0.w * (cf + f0.w);
    o1.x = v1.x * (cf + f1.x); o1.y = v1.y * (cf + f1.y);
    o1.z = v1.z * (cf + f1.z); o1.w = v1.w * (cf + f1.w);
    o2.x = v2.x * (cf + f2.x); o2.y = v2.y * (cf + f2.y);
    o2.z = v2.z * (cf + f2.z); o2.w = v2.w * (cf + f2.w);
    o3.x = v3.x * (cf + f3.x); o3.y = v3.y * (cf + f3.y);
    o3.z = v3.z * (cf + f3.z); o3.w = v3.w * (cf + f3.w);

    __stcs(out + base + t, o0);
    __stcs(out + base + 256 + t, o1);
    __stcs(out + base + 512 + t, o2);
    __stcs(out + base + 768 + t, o3);
}

// ---------------------------------------------------------------------------
// Launch helpers: PDL (programmatic stream serialization) on kernels 2-4.
// ---------------------------------------------------------------------------
template <typename F, typename... Args>
static void launch_pdl(F func, dim3 grid, dim3 block, Args... args) {
    cudaLaunchConfig_t cfg = {};
    cfg.gridDim = grid;
    cfg.blockDim = block;
    cfg.dynamicSmemBytes = 0;
    cfg.stream = 0;
    cudaLaunchAttribute attr[1];
    attr[0].id = cudaLaunchAttributeProgrammaticStreamSerialization;
    attr[0].val.programmaticStreamSerializationAllowed = 1;
    cfg.attrs = attr;
    cfg.numAttrs = 1;
    cudaLaunchKernelEx(&cfg, func, args...);
}

extern "C" void kernel_launch(void* const* d_in, const int* in_sizes, int n_in,
                              void* d_out, int out_size) {
    const float* x    = (const float*)d_in[0];   // [16,256,128,128]
    const float* Wm   = (const float*)d_in[1];   // [256,256]
    const float* bias = (const float*)d_in[2];   // [256]
    float* out = (float*)d_out;

    mean_cf_kernel<<<4096 + 64, 64>>>((const float4*)x, Wm, bias);
    launch_pdl(dft_stage1, dim3(32, B_), dim3(128));
    launch_pdl(dft_stage2, dim3(32, B_), dim3(128));
    launch_pdl(out_kernel, dim3((B_ * C_ * HW4) / 1024), dim3(256),
               (const float4*)x, (float4*)out);
}

// round 15
// speedup vs baseline: 1.0037x; 1.0037x over previous
#include <cuda_runtime.h>
#include <math.h>
#include <stdint.h>

// Problem dims
#define B_  16
#define C_  256
#define H_  128
#define W_  128
#define HW  (H_ * W_)         // 16384
#define HW4 (HW / 4)          // 4096 float4 per plane
#define PH  (B_ * HW)         // phase stride in g_mp (262144 floats)

// Device scratch (no allocation allowed)
__device__ float g_mp[4 * PH];        // partial channel sums [phase][b][h][w]
__device__ float g_cf[B_ * C_];       // sigmoid gate [b][c]
__device__ float g_Pt[B_ * HW];       // (C*m) transposed: [b][w][u]
__device__ float g_Qt[B_ * HW];       // (S*m) transposed: [b][w][u]
__device__ float g_sf[B_ * HW];       // sf [b][h][w]

// ---- PDL controls -----------------------------------------------------------
__device__ __forceinline__ void grid_wait() {
    asm volatile("griddepcontrol.wait;" ::: "memory");
}
__device__ __forceinline__ void grid_launch_dependents() {
    asm volatile("griddepcontrol.launch_dependents;" ::: "memory");
}

// ---- packed f32x2 helpers (Blackwell) --------------------------------------
__device__ __forceinline__ uint64_t pk2(float lo, float hi) {
    uint64_t r;
    asm("mov.b64 %0, {%1, %2};" : "=l"(r) : "f"(lo), "f"(hi));
    return r;
}
__device__ __forceinline__ void upk2(uint64_t v, float& lo, float& hi) {
    asm("mov.b64 {%0, %1}, %2;" : "=f"(lo), "=f"(hi) : "l"(v));
}
__device__ __forceinline__ uint64_t fma2(uint64_t a, uint64_t b, uint64_t c) {
    uint64_t r;
    asm("fma.rn.f32x2 %0, %1, %2, %3;" : "=l"(r) : "l"(a), "l"(b), "l"(c));
    return r;
}
__device__ __forceinline__ void lds_v2u64(unsigned addr, uint64_t& a, uint64_t& b) {
    asm("ld.shared.v2.u64 {%0, %1}, [%2];" : "=l"(a), "=l"(b) : "r"(addr));
}

// ---------------------------------------------------------------------------
// Kernel 1 (merged): blocks 0..4095  -> partial channel sums (64 ch each)
//                    blocks 4096..4159 -> cf gate
// 4 accumulator streams (measured MLP optimum); channel loop fully unrolled
// so ptxas can front-hoist extra load batches without more accumulators.
// ---------------------------------------------------------------------------
__global__ void mean_cf_kernel(const float4* __restrict__ x,
                               const float* __restrict__ Wm,
                               const float* __restrict__ bias) {
    if (blockIdx.x < 4096) {
        int phase = blockIdx.x >> 10;                      // 0..3
        int t = (blockIdx.x & 1023) * 64 + threadIdx.x;    // 0 .. 65535
        int b = t >> 12;
        int pos = t & 4095;
        int c0 = phase * 64;
        const float4* p = x + (size_t)b * C_ * HW4 + (size_t)c0 * HW4 + pos;
        float4 a0 = make_float4(0.f, 0.f, 0.f, 0.f);
        float4 a1 = make_float4(0.f, 0.f, 0.f, 0.f);
        float4 a2 = make_float4(0.f, 0.f, 0.f, 0.f);
        float4 a3 = make_float4(0.f, 0.f, 0.f, 0.f);
#pragma unroll
        for (int c = 0; c < 64; c += 4) {
            float4 v0 = p[(size_t)(c + 0) * HW4];
            float4 v1 = p[(size_t)(c + 1) * HW4];
            float4 v2 = p[(size_t)(c + 2) * HW4];
            float4 v3 = p[(size_t)(c + 3) * HW4];
            a0.x += v0.x; a0.y += v0.y; a0.z += v0.z; a0.w += v0.w;
            a1.x += v1.x; a1.y += v1.y; a1.z += v1.z; a1.w += v1.w;
            a2.x += v2.x; a2.y += v2.y; a2.z += v2.z; a2.w += v2.w;
            a3.x += v3.x; a3.y += v3.y; a3.z += v3.z; a3.w += v3.w;
        }
        float4 acc;
        acc.x = (a0.x + a1.x) + (a2.x + a3.x);
        acc.y = (a0.y + a1.y) + (a2.y + a3.y);
        acc.z = (a0.z + a1.z) + (a2.z + a3.z);
        acc.w = (a0.w + a1.w) + (a2.w + a3.w);
        ((float4*)g_mp)[phase * (PH / 4) + t] = acc;
        grid_launch_dependents();
    } else {
        __shared__ __align__(16) float xs[C_];
        int cb = blockIdx.x - 4096;
        int b  = cb >> 2;
        int c0 = (cb & 3) * 64;
        const float* xf = (const float*)x;
#pragma unroll
        for (int k = 0; k < 4; ++k) {
            int ch = threadIdx.x * 4 + k;
            xs[ch] = xf[((size_t)(b * C_ + ch)) * HW];     // x[b,ch,0,0]
        }
        __syncthreads();
        int c = c0 + threadIdx.x;
        float acc = bias[c];
        const float4* wr = (const float4*)(Wm + (size_t)c * C_);
        const float4* xv = (const float4*)xs;
#pragma unroll 8
        for (int k = 0; k < C_ / 4; ++k) {
            float4 w4 = wr[k];
            float4 x4 = xv[k];
            acc += w4.x * x4.x + w4.y * x4.y + w4.z * x4.z + w4.w * x4.w;
        }
        g_cf[b * C_ + c] = 1.0f / (1.0f + expf(-acc));
        grid_launch_dependents();
    }
}

// ---------------------------------------------------------------------------
// DFT stage 1: twiddle preamble runs BEFORE the PDL wait (overlaps mean tail).
// ---------------------------------------------------------------------------
__global__ void dft_stage1(void) {
    __shared__ float twc[128], tws[128];
    __shared__ __align__(16) float mr[128][4];
    __shared__ __align__(16) float me[64][4];   // h = 1..63 used
    __shared__ __align__(16) float mo[64][4];

    int b  = blockIdx.y;
    int wt = blockIdx.x;           // w-tile (4 wide)
    int tid = threadIdx.x;         // 0..127
    int u = tid;

    // --- preamble (no dependency on mean) ---
    {
        float s, c;
        sincospif((float)tid * (1.0f / 64.0f), &s, &c);   // e^{i*2pi*tid/128}
        twc[tid] = c; tws[tid] = s;
    }
    grid_wait();
    // --- dependent loads ---
    {
        const float* mb = g_mp + (size_t)b * HW + wt * 4 + tid * W_;
        float4 p0 = *(const float4*)(mb);
        float4 p1 = *(const float4*)(mb + PH);
        float4 p2 = *(const float4*)(mb + 2 * PH);
        float4 p3 = *(const float4*)(mb + 3 * PH);
        const float sc = 1.0f / 256.0f;
        mr[tid][0] = ((p0.x + p1.x) + (p2.x + p3.x)) * sc;
        mr[tid][1] = ((p0.y + p1.y) + (p2.y + p3.y)) * sc;
        mr[tid][2] = ((p0.z + p1.z) + (p2.z + p3.z)) * sc;
        mr[tid][3] = ((p0.w + p1.w) + (p2.w + p3.w)) * sc;
    }
    __syncthreads();
    if (tid < 63) {
        int h = tid + 1;
#pragma unroll
        for (int c = 0; c < 4; ++c) {
            float a = mr[h][c], d = mr[128 - h][c];
            me[h][c] = a + d;
            mo[h][c] = a - d;
        }
    }
    __syncthreads();

    float cj[8], sj[8], cg[8], sg[8];
    cj[0] = 1.0f; sj[0] = 0.0f;
    cg[0] = 1.0f; sg[0] = 0.0f;
#pragma unroll
    for (int j = 1; j < 8; ++j) {
        int idx = (u * j) & 127;
        cj[j] = twc[idx]; sj[j] = tws[idx];
    }
#pragma unroll
    for (int g = 1; g < 8; ++g) {
        int idx = (u * g * 8) & 127;
        cg[g] = twc[idx]; sg[g] = tws[idx];
    }

    float sgn = (u & 1) ? -1.0f : 1.0f;
    uint64_t aP0 = pk2(mr[0][0] + sgn * mr[64][0], mr[0][1] + sgn * mr[64][1]);
    uint64_t aP1 = pk2(mr[0][2] + sgn * mr[64][2], mr[0][3] + sgn * mr[64][3]);
    uint64_t aQ0 = pk2(0.f, 0.f);
    uint64_t aQ1 = aQ0;

    unsigned sme = (unsigned)__cvta_generic_to_shared(&me[0][0]);
    unsigned smo = (unsigned)__cvta_generic_to_shared(&mo[0][0]);

#pragma unroll
    for (int h = 1; h < 64; ++h) {
        int g = h >> 3, j = h & 7;
        float cw = cg[g] * cj[j] - sg[g] * sj[j];
        float sw = sg[g] * cj[j] + cg[g] * sj[j];
        uint64_t cwp = pk2(cw, cw);
        uint64_t swp = pk2(sw, sw);
        uint64_t e0, e1, o0, o1;
        lds_v2u64(sme + h * 16, e0, e1);
        lds_v2u64(smo + h * 16, o0, o1);
        aP0 = fma2(cwp, e0, aP0);
        aP1 = fma2(cwp, e1, aP1);
        aQ0 = fma2(swp, o0, aQ0);
        aQ1 = fma2(swp, o1, aQ1);
    }

    float p0, p1, p2, p3, q0, q1, q2, q3;
    upk2(aP0, p0, p1); upk2(aP1, p2, p3);
    upk2(aQ0, q0, q1); upk2(aQ1, q2, q3);

    size_t base = (size_t)b * HW;
    int w0 = wt * 4;
    g_Pt[base + (w0 + 0) * 128 + u] = p0;
    g_Pt[base + (w0 + 1) * 128 + u] = p1;
    g_Pt[base + (w0 + 2) * 128 + u] = p2;
    g_Pt[base + (w0 + 3) * 128 + u] = p3;
    g_Qt[base + (w0 + 0) * 128 + u] = q0;
    g_Qt[base + (w0 + 1) * 128 + u] = q1;
    g_Qt[base + (w0 + 2) * 128 + u] = q2;
    g_Qt[base + (w0 + 3) * 128 + u] = q3;
    grid_launch_dependents();
}

// ---------------------------------------------------------------------------
// DFT stage 2: twiddle preamble before PDL wait (overlaps dft_stage1).
// ---------------------------------------------------------------------------
__global__ void dft_stage2(void) {
    __shared__ float twc[128], tws[128];
    __shared__ __align__(16) float pr[128][4];
    __shared__ __align__(16) float qr[128][4];
    __shared__ __align__(16) float pe[64][4];
    __shared__ __align__(16) float qo[64][4];

    int b  = blockIdx.y;
    int ut = blockIdx.x;            // u-tile (4 wide)
    int tid = threadIdx.x;          // 0..127
    int v = tid;

    {
        float s, c;
        sincospif((float)tid * (1.0f / 64.0f), &s, &c);
        twc[tid] = c; tws[tid] = s;
    }
    grid_wait();
    {
        const float* pb = g_Pt + (size_t)b * HW + ut * 4;
        const float* qb = g_Qt + (size_t)b * HW + ut * 4;
        float4 pv = *(const float4*)(pb + tid * 128);
        float4 qv = *(const float4*)(qb + tid * 128);
        pr[tid][0] = pv.x; pr[tid][1] = pv.y; pr[tid][2] = pv.z; pr[tid][3] = pv.w;
        qr[tid][0] = qv.x; qr[tid][1] = qv.y; qr[tid][2] = qv.z; qr[tid][3] = qv.w;
    }
    __syncthreads();
    if (tid < 63) {
        int w = tid + 1;
#pragma unroll
        for (int c = 0; c < 4; ++c) {
            pe[w][c] = pr[w][c] + pr[128 - w][c];
            qo[w][c] = qr[w][c] - qr[128 - w][c];
        }
    }
    __syncthreads();

    float cj[8], sj[8], cg[8], sg[8];
    cj[0] = 1.0f; sj[0] = 0.0f;
    cg[0] = 1.0f; sg[0] = 0.0f;
#pragma unroll
    for (int j = 1; j < 8; ++j) {
        int idx = (v * j) & 127;
        cj[j] = twc[idx]; sj[j] = tws[idx];
    }
#pragma unroll
    for (int g = 1; g < 8; ++g) {
        int idx = (v * g * 8) & 127;
        cg[g] = twc[idx]; sg[g] = tws[idx];
    }

    float sgn = (v & 1) ? -1.0f : 1.0f;
    uint64_t a0 = pk2(pr[0][0] + sgn * pr[64][0], pr[0][1] + sgn * pr[64][1]);
    uint64_t a1 = pk2(pr[0][2] + sgn * pr[64][2], pr[0][3] + sgn * pr[64][3]);

    unsigned spe = (unsigned)__cvta_generic_to_shared(&pe[0][0]);
    unsigned sqo = (unsigned)__cvta_generic_to_shared(&qo[0][0]);

#pragma unroll
    for (int w = 1; w < 64; ++w) {
        int g = w >> 3, j = w & 7;
        float cw = cg[g] * cj[j] - sg[g] * sj[j];
        float sw = sg[g] * cj[j] + cg[g] * sj[j];
        uint64_t cwp = pk2(cw, cw);
        uint64_t nswp = pk2(-sw, -sw);
        uint64_t e0, e1, o0, o1;
        lds_v2u64(spe + w * 16, e0, e1);
        lds_v2u64(sqo + w * 16, o0, o1);
        a0 = fma2(cwp, e0, a0);
        a1 = fma2(cwp, e1, a1);
        a0 = fma2(nswp, o0, a0);
        a1 = fma2(nswp, o1, a1);
    }

    float r0, r1, r2, r3;
    upk2(a0, r0, r1); upk2(a1, r2, r3);

    size_t base = (size_t)b * HW;
    int u0 = ut * 4;
    g_sf[base + (u0 + 0) * 128 + v] = r0;   // coalesced in v
    g_sf[base + (u0 + 1) * 128 + v] = r1;
    g_sf[base + (u0 + 2) * 128 + v] = r2;
    g_sf[base + (u0 + 3) * 128 + v] = r3;
    grid_launch_dependents();
}

// ---------------------------------------------------------------------------
// Kernel 4: out = x * (cf + sf). x loads issued BEFORE the PDL wait.
// ---------------------------------------------------------------------------
__global__ void out_kernel(const float4* __restrict__ x, float4* __restrict__ out) {
    int chunk = gridDim.x - 1 - blockIdx.x;
    int base = chunk * 1024;                    // chunk start (plane-aligned /4)
    int plane = base >> 12;                     // (b*256 + c), constant per block
    int b = plane >> 8;
    int t = threadIdx.x;

    float4 v0 = __ldcs(x + base + t);
    float4 v1 = __ldcs(x + base + 256 + t);
    float4 v2 = __ldcs(x + base + 512 + t);
    float4 v3 = __ldcs(x + base + 768 + t);

    grid_wait();

    float cf = g_cf[plane];
    const float4* sf4 = (const float4*)g_sf + b * HW4 + (base & 4095);
    float4 f0 = sf4[t];
    float4 f1 = sf4[256 + t];
    float4 f2 = sf4[512 + t];
    float4 f3 = sf4[768 + t];

    float4 o0, o1, o2, o3;
    o0.x = v0.x * (cf + f0.x); o0.y = v0.y * (cf + f0.y);
    o0.z = v0.z * (cf + f0.z); o0.w = v0.w * (cf + f0.w);
    o1.x = v1.x * (cf + f1.x); o1.y = v1.y * (cf + f1.y);
    o1.z = v1.z * (cf + f1.z); o1.w = v1.w * (cf + f1.w);
    o2.x = v2.x * (cf + f2.x); o2.y = v2.y * (cf + f2.y);
    o2.z = v2.z * (cf + f2.z); o2.w = v2.w * (cf + f2.w);
    o3.x = v3.x * (cf + f3.x); o3.y = v3.y * (cf + f3.y);
    o3.z = v3.z * (cf + f3.z); o3.w = v3.w * (cf + f3.w);

    __stcs(out + base + t, o0);
    __stcs(out + base + 256 + t, o1);
    __stcs(out + base + 512 + t, o2);
    __stcs(out + base + 768 + t, o3);
}

// ---------------------------------------------------------------------------
// Launch helpers: PDL (programmatic stream serialization) on kernels 2-4.
// ---------------------------------------------------------------------------
template <typename F, typename... Args>
static void launch_pdl(F func, dim3 grid, dim3 block, Args... args) {
    cudaLaunchConfig_t cfg = {};
    cfg.gridDim = grid;
    cfg.blockDim = block;
    cfg.dynamicSmemBytes = 0;
    cfg.stream = 0;
    cudaLaunchAttribute attr[1];
    attr[0].id = cudaLaunchAttributeProgrammaticStreamSerialization;
    attr[0].val.programmaticStreamSerializationAllowed = 1;
    cfg.attrs = attr;
    cfg.numAttrs = 1;
    cudaLaunchKernelEx(&cfg, func, args...);
}

extern "C" void kernel_launch(void* const* d_in, const int* in_sizes, int n_in,
                              void* d_out, int out_size) {
    const float* x    = (const float*)d_in[0];   // [16,256,128,128]
    const float* Wm   = (const float*)d_in[1];   // [256,256]
    const float* bias = (const float*)d_in[2];   // [256]
    float* out = (float*)d_out;

    mean_cf_kernel<<<4096 + 64, 64>>>((const float4*)x, Wm, bias);
    launch_pdl(dft_stage1, dim3(32, B_), dim3(128));
    launch_pdl(dft_stage2, dim3(32, B_), dim3(128));
    launch_pdl(out_kernel, dim3((B_ * C_ * HW4) / 1024), dim3(256),
               (const float4*)x, (float4*)out);
}

// round 17
// speedup vs baseline: 1.0310x; 1.0272x over previous
#include <cuda_runtime.h>
#include <math.h>
#include <stdint.h>

// Problem dims
#define B_  16
#define C_  256
#define H_  128
#define W_  128
#define HW  (H_ * W_)         // 16384
#define HW4 (HW / 4)          // 4096 float4 per plane
#define PH  (B_ * HW)         // phase stride in g_mp (262144 floats)

// Device scratch (no allocation allowed)
__device__ float g_mp[4 * PH];        // partial channel sums [phase][b][h][w]
__device__ float g_cf[B_ * C_];       // sigmoid gate [b][c]
__device__ float g_Pt[B_ * HW];       // (C*m) transposed: [b][w][u]
__device__ float g_Qt[B_ * HW];       // (S*m) transposed: [b][w][u]
__device__ float g_sf[B_ * HW];       // sf [b][h][w]

// ---- PDL controls -----------------------------------------------------------
__device__ __forceinline__ void grid_wait() {
    asm volatile("griddepcontrol.wait;" ::: "memory");
}
__device__ __forceinline__ void grid_launch_dependents() {
    asm volatile("griddepcontrol.launch_dependents;" ::: "memory");
}

// ---- packed f32x2 helpers (Blackwell) --------------------------------------
__device__ __forceinline__ uint64_t pk2(float lo, float hi) {
    uint64_t r;
    asm("mov.b64 %0, {%1, %2};" : "=l"(r) : "f"(lo), "f"(hi));
    return r;
}
__device__ __forceinline__ void upk2(uint64_t v, float& lo, float& hi) {
    asm("mov.b64 {%0, %1}, %2;" : "=f"(lo), "=f"(hi) : "l"(v));
}
__device__ __forceinline__ uint64_t fma2(uint64_t a, uint64_t b, uint64_t c) {
    uint64_t r;
    asm("fma.rn.f32x2 %0, %1, %2, %3;" : "=l"(r) : "l"(a), "l"(b), "l"(c));
    return r;
}
__device__ __forceinline__ void lds_v2u64(unsigned addr, uint64_t& a, uint64_t& b) {
    asm("ld.shared.v2.u64 {%0, %1}, [%2];" : "=l"(a), "=l"(b) : "r"(addr));
}

// ---------------------------------------------------------------------------
// Kernel 1 (merged): blocks 0..4095  -> partial channel sums (64 ch each)
//                    blocks 4096..4159 -> cf gate
// 4 accumulator streams x unroll 8 -> 32 independent loads in flight/thread
// (the measured MLP optimum; 16 and 48 both measured slower).
// ---------------------------------------------------------------------------
__global__ void mean_cf_kernel(const float4* __restrict__ x,
                               const float* __restrict__ Wm,
                               const float* __restrict__ bias) {
    if (blockIdx.x < 4096) {
        int phase = blockIdx.x >> 10;                      // 0..3
        int t = (blockIdx.x & 1023) * 64 + threadIdx.x;    // 0 .. 65535
        int b = t >> 12;
        int pos = t & 4095;
        int c0 = phase * 64;
        const float4* p = x + (size_t)b * C_ * HW4 + (size_t)c0 * HW4 + pos;
        float4 a0 = make_float4(0.f, 0.f, 0.f, 0.f);
        float4 a1 = make_float4(0.f, 0.f, 0.f, 0.f);
        float4 a2 = make_float4(0.f, 0.f, 0.f, 0.f);
        float4 a3 = make_float4(0.f, 0.f, 0.f, 0.f);
#pragma unroll 8
        for (int c = 0; c < 64; c += 4) {
            float4 v0 = p[(size_t)(c + 0) * HW4];
            float4 v1 = p[(size_t)(c + 1) * HW4];
            float4 v2 = p[(size_t)(c + 2) * HW4];
            float4 v3 = p[(size_t)(c + 3) * HW4];
            a0.x += v0.x; a0.y += v0.y; a0.z += v0.z; a0.w += v0.w;
            a1.x += v1.x; a1.y += v1.y; a1.z += v1.z; a1.w += v1.w;
            a2.x += v2.x; a2.y += v2.y; a2.z += v2.z; a2.w += v2.w;
            a3.x += v3.x; a3.y += v3.y; a3.z += v3.z; a3.w += v3.w;
        }
        float4 acc;
        acc.x = (a0.x + a1.x) + (a2.x + a3.x);
        acc.y = (a0.y + a1.y) + (a2.y + a3.y);
        acc.z = (a0.z + a1.z) + (a2.z + a3.z);
        acc.w = (a0.w + a1.w) + (a2.w + a3.w);
        ((float4*)g_mp)[phase * (PH / 4) + t] = acc;
        grid_launch_dependents();
    } else {
        __shared__ __align__(16) float xs[C_];
        int cb = blockIdx.x - 4096;
        int b  = cb >> 2;
        int c0 = (cb & 3) * 64;
        const float* xf = (const float*)x;
#pragma unroll
        for (int k = 0; k < 4; ++k) {
            int ch = threadIdx.x * 4 + k;
            xs[ch] = xf[((size_t)(b * C_ + ch)) * HW];     // x[b,ch,0,0]
        }
        __syncthreads();
        int c = c0 + threadIdx.x;
        float acc = bias[c];
        const float4* wr = (const float4*)(Wm + (size_t)c * C_);
        const float4* xv = (const float4*)xs;
#pragma unroll 8
        for (int k = 0; k < C_ / 4; ++k) {
            float4 w4 = wr[k];
            float4 x4 = xv[k];
            acc += w4.x * x4.x + w4.y * x4.y + w4.z * x4.z + w4.w * x4.w;
        }
        g_cf[b * C_ + c] = 1.0f / (1.0f + expf(-acc));
        grid_launch_dependents();
    }
}

// ---------------------------------------------------------------------------
// DFT stage 1: twiddle preamble runs BEFORE the PDL wait (overlaps mean tail).
// ---------------------------------------------------------------------------
__global__ void dft_stage1(void) {
    __shared__ float twc[128], tws[128];
    __shared__ __align__(16) float mr[128][4];
    __shared__ __align__(16) float me[64][4];   // h = 1..63 used
    __shared__ __align__(16) float mo[64][4];

    int b  = blockIdx.y;
    int wt = blockIdx.x;           // w-tile (4 wide)
    int tid = threadIdx.x;         // 0..127
    int u = tid;

    // --- preamble (no dependency on mean) ---
    {
        float s, c;
        sincospif((float)tid * (1.0f / 64.0f), &s, &c);   // e^{i*2pi*tid/128}
        twc[tid] = c; tws[tid] = s;
    }
    grid_wait();
    // --- dependent loads ---
    {
        const float* mb = g_mp + (size_t)b * HW + wt * 4 + tid * W_;
        float4 p0 = *(const float4*)(mb);
        float4 p1 = *(const float4*)(mb + PH);
        float4 p2 = *(const float4*)(mb + 2 * PH);
        float4 p3 = *(const float4*)(mb + 3 * PH);
        const float sc = 1.0f / 256.0f;
        mr[tid][0] = ((p0.x + p1.x) + (p2.x + p3.x)) * sc;
        mr[tid][1] = ((p0.y + p1.y) + (p2.y + p3.y)) * sc;
        mr[tid][2] = ((p0.z + p1.z) + (p2.z + p3.z)) * sc;
        mr[tid][3] = ((p0.w + p1.w) + (p2.w + p3.w)) * sc;
    }
    __syncthreads();
    if (tid < 63) {
        int h = tid + 1;
#pragma unroll
        for (int c = 0; c < 4; ++c) {
            float a = mr[h][c], d = mr[128 - h][c];
            me[h][c] = a + d;
            mo[h][c] = a - d;
        }
    }
    __syncthreads();

    float cj[8], sj[8], cg[8], sg[8];
    cj[0] = 1.0f; sj[0] = 0.0f;
    cg[0] = 1.0f; sg[0] = 0.0f;
#pragma unroll
    for (int j = 1; j < 8; ++j) {
        int idx = (u * j) & 127;
        cj[j] = twc[idx]; sj[j] = tws[idx];
    }
#pragma unroll
    for (int g = 1; g < 8; ++g) {
        int idx = (u * g * 8) & 127;
        cg[g] = twc[idx]; sg[g] = tws[idx];
    }

    float sgn = (u & 1) ? -1.0f : 1.0f;
    uint64_t aP0 = pk2(mr[0][0] + sgn * mr[64][0], mr[0][1] + sgn * mr[64][1]);
    uint64_t aP1 = pk2(mr[0][2] + sgn * mr[64][2], mr[0][3] + sgn * mr[64][3]);
    uint64_t aQ0 = pk2(0.f, 0.f);
    uint64_t aQ1 = aQ0;

    unsigned sme = (unsigned)__cvta_generic_to_shared(&me[0][0]);
    unsigned smo = (unsigned)__cvta_generic_to_shared(&mo[0][0]);

#pragma unroll
    for (int h = 1; h < 64; ++h) {
        int g = h >> 3, j = h & 7;
        float cw = cg[g] * cj[j] - sg[g] * sj[j];
        float sw = sg[g] * cj[j] + cg[g] * sj[j];
        uint64_t cwp = pk2(cw, cw);
        uint64_t swp = pk2(sw, sw);
        uint64_t e0, e1, o0, o1;
        lds_v2u64(sme + h * 16, e0, e1);
        lds_v2u64(smo + h * 16, o0, o1);
        aP0 = fma2(cwp, e0, aP0);
        aP1 = fma2(cwp, e1, aP1);
        aQ0 = fma2(swp, o0, aQ0);
        aQ1 = fma2(swp, o1, aQ1);
    }

    float p0, p1, p2, p3, q0, q1, q2, q3;
    upk2(aP0, p0, p1); upk2(aP1, p2, p3);
    upk2(aQ0, q0, q1); upk2(aQ1, q2, q3);

    size_t base = (size_t)b * HW;
    int w0 = wt * 4;
    g_Pt[base + (w0 + 0) * 128 + u] = p0;
    g_Pt[base + (w0 + 1) * 128 + u] = p1;
    g_Pt[base + (w0 + 2) * 128 + u] = p2;
    g_Pt[base + (w0 + 3) * 128 + u] = p3;
    g_Qt[base + (w0 + 0) * 128 + u] = q0;
    g_Qt[base + (w0 + 1) * 128 + u] = q1;
    g_Qt[base + (w0 + 2) * 128 + u] = q2;
    g_Qt[base + (w0 + 3) * 128 + u] = q3;
    grid_launch_dependents();
}

// ---------------------------------------------------------------------------
// DFT stage 2: twiddle preamble before PDL wait (overlaps dft_stage1).
// ---------------------------------------------------------------------------
__global__ void dft_stage2(void) {
    __shared__ float twc[128], tws[128];
    __shared__ __align__(16) float pr[128][4];
    __shared__ __align__(16) float qr[128][4];
    __shared__ __align__(16) float pe[64][4];
    __shared__ __align__(16) float qo[64][4];

    int b  = blockIdx.y;
    int ut = blockIdx.x;            // u-tile (4 wide)
    int tid = threadIdx.x;          // 0..127
    int v = tid;

    {
        float s, c;
        sincospif((float)tid * (1.0f / 64.0f), &s, &c);
        twc[tid] = c; tws[tid] = s;
    }
    grid_wait();
    {
        const float* pb = g_Pt + (size_t)b * HW + ut * 4;
        const float* qb = g_Qt + (size_t)b * HW + ut * 4;
        float4 pv = *(const float4*)(pb + tid * 128);
        float4 qv = *(const float4*)(qb + tid * 128);
        pr[tid][0] = pv.x; pr[tid][1] = pv.y; pr[tid][2] = pv.z; pr[tid][3] = pv.w;
        qr[tid][0] = qv.x; qr[tid][1] = qv.y; qr[tid][2] = qv.z; qr[tid][3] = qv.w;
    }
    __syncthreads();
    if (tid < 63) {
        int w = tid + 1;
#pragma unroll
        for (int c = 0; c < 4; ++c) {
            pe[w][c] = pr[w][c] + pr[128 - w][c];
            qo[w][c] = qr[w][c] - qr[128 - w][c];
        }
    }
    __syncthreads();

    float cj[8], sj[8], cg[8], sg[8];
    cj[0] = 1.0f; sj[0] = 0.0f;
    cg[0] = 1.0f; sg[0] = 0.0f;
#pragma unroll
    for (int j = 1; j < 8; ++j) {
        int idx = (v * j) & 127;
        cj[j] = twc[idx]; sj[j] = tws[idx];
    }
#pragma unroll
    for (int g = 1; g < 8; ++g) {
        int idx = (v * g * 8) & 127;
        cg[g] = twc[idx]; sg[g] = tws[idx];
    }

    float sgn = (v & 1) ? -1.0f : 1.0f;
    uint64_t a0 = pk2(pr[0][0] + sgn * pr[64][0], pr[0][1] + sgn * pr[64][1]);
    uint64_t a1 = pk2(pr[0][2] + sgn * pr[64][2], pr[0][3] + sgn * pr[64][3]);

    unsigned spe = (unsigned)__cvta_generic_to_shared(&pe[0][0]);
    unsigned sqo = (unsigned)__cvta_generic_to_shared(&qo[0][0]);

#pragma unroll
    for (int w = 1; w < 64; ++w) {
        int g = w >> 3, j = w & 7;
        float cw = cg[g] * cj[j] - sg[g] * sj[j];
        float sw = sg[g] * cj[j] + cg[g] * sj[j];
        uint64_t cwp = pk2(cw, cw);
        uint64_t nswp = pk2(-sw, -sw);
        uint64_t e0, e1, o0, o1;
        lds_v2u64(spe + w * 16, e0, e1);
        lds_v2u64(sqo + w * 16, o0, o1);
        a0 = fma2(cwp, e0, a0);
        a1 = fma2(cwp, e1, a1);
        a0 = fma2(nswp, o0, a0);
        a1 = fma2(nswp, o1, a1);
    }

    float r0, r1, r2, r3;
    upk2(a0, r0, r1); upk2(a1, r2, r3);

    size_t base = (size_t)b * HW;
    int u0 = ut * 4;
    g_sf[base + (u0 + 0) * 128 + v] = r0;   // coalesced in v
    g_sf[base + (u0 + 1) * 128 + v] = r1;
    g_sf[base + (u0 + 2) * 128 + v] = r2;
    g_sf[base + (u0 + 3) * 128 + v] = r3;
    grid_launch_dependents();
}

// ---------------------------------------------------------------------------
// Kernel 4: out = x * (cf + sf). x loads issued BEFORE the PDL wait.
// ---------------------------------------------------------------------------
__global__ void out_kernel(const float4* __restrict__ x, float4* __restrict__ out) {
    int chunk = gridDim.x - 1 - blockIdx.x;
    int base = chunk * 1024;                    // chunk start (plane-aligned /4)
    int plane = base >> 12;                     // (b*256 + c), constant per block
    int b = plane >> 8;
    int t = threadIdx.x;

    float4 v0 = __ldcs(x + base + t);
    float4 v1 = __ldcs(x + base + 256 + t);
    float4 v2 = __ldcs(x + base + 512 + t);
    float4 v3 = __ldcs(x + base + 768 + t);

    grid_wait();

    float cf = g_cf[plane];
    const float4* sf4 = (const float4*)g_sf + b * HW4 + (base & 4095);
    float4 f0 = sf4[t];
    float4 f1 = sf4[256 + t];
    float4 f2 = sf4[512 + t];
    float4 f3 = sf4[768 + t];

    float4 o0, o1, o2, o3;
    o0.x = v0.x * (cf + f0.x); o0.y = v0.y * (cf + f0.y);
    o0.z = v0.z * (cf + f0.z); o0.w = v0.w * (cf + f0.w);
    o1.x = v1.x * (cf + f1.x); o1.y = v1.y * (cf + f1.y);
    o1.z = v1.z * (cf + f1.z); o1.w = v1.w * (cf + f1.w);
    o2.x = v2.x * (cf + f2.x); o2.y = v2.y * (cf + f2.y);
    o2.z = v2.z * (cf + f2.z); o2.w = v2.w * (cf + f2.w);
    o3.x = v3.x * (cf + f3.x); o3.y = v3.y * (cf + f3.y);
    o3.z = v3.z * (cf + f3.z); o3.w = v3.w * (cf + f3.w);

    __stcs(out + base + t, o0);
    __stcs(out + base + 256 + t, o1);
    __stcs(out + base + 512 + t, o2);
    __stcs(out + base + 768 + t, o3);
}

// ---------------------------------------------------------------------------
// Launch helpers: PDL (programmatic stream serialization) on kernels 2-4.
// ---------------------------------------------------------------------------
template <typename F, typename... Args>
static void launch_pdl(F func, dim3 grid, dim3 block, Args... args) {
    cudaLaunchConfig_t cfg = {};
    cfg.gridDim = grid;
    cfg.blockDim = block;
    cfg.dynamicSmemBytes = 0;
    cfg.stream = 0;
    cudaLaunchAttribute attr[1];
    attr[0].id = cudaLaunchAttributeProgrammaticStreamSerialization;
    attr[0].val.programmaticStreamSerializationAllowed = 1;
    cfg.attrs = attr;
    cfg.numAttrs = 1;
    cudaLaunchKernelEx(&cfg, func, args...);
}

extern "C" void kernel_launch(void* const* d_in, const int* in_sizes, int n_in,
                              void* d_out, int out_size) {
    const float* x    = (const float*)d_in[0];   // [16,256,128,128]
    const float* Wm   = (const float*)d_in[1];   // [256,256]
    const float* bias = (const float*)d_in[2];   // [256]
    float* out = (float*)d_out;

    mean_cf_kernel<<<4096 + 64, 64>>>((const float4*)x, Wm, bias);
    launch_pdl(dft_stage1, dim3(32, B_), dim3(128));
    launch_pdl(dft_stage2, dim3(32, B_), dim3(128));
    launch_pdl(out_kernel, dim3((B_ * C_ * HW4) / 1024), dim3(256),
               (const float4*)x, (float4*)out);
}